// round 12
// baseline (speedup 1.0000x reference)
#include <cuda_runtime.h>
#include <cuda_fp16.h>
#include <cstdint>

// ---------------------------------------------------------------------------
// QKVProjectedLinear, single-launch, warp-specialized, 2 CTAs/SM:
//   G_k = (B_k Ws_k^T B_k^T) A_k^T  [64,1024]   (phase-0 CTAs 256..295)
//   t1  = x @ A_all                 [16384,192] (stage 1: x fp16 hi/lo, A fp16)
//   out_k = t1_k @ G_k              (stage 2: t1 fp16 hi/lo, G fp16)
// 296 CTAs x 384 thr (occ 2): 256 workers (64-row tiles), 40 phase-0.
// Worker: warps 0-7 consumers (4Mx2N HMMA), warps 8-11 producers.
// ---------------------------------------------------------------------------

#define K3 3
#define DL 1024
#define DS 768
#define RK 64
#define NJ 192
#define DOUT 3072
#define NWORK 256
#define NP0 40
#define NTHR 384

// ------------------------- device scratch ----------------------------------
__device__ __align__(16) float g_U[K3*RK*DS];
__device__ __align__(16) float g_Vp[K3*4*RK*RK];
__device__ __align__(16) __half g_Af[DL*NJ];             // A_all fp16 [1024,192]
__device__ __align__(16) __half g_G[K3*RK*DL];           // G fp16 [3,64,1024]
__device__ int c_A, c_U, c_V, c_G;

__device__ __forceinline__ void splith(float v, __half& h, __half& l){
    h = __float2half(v);
    l = __float2half(v - __half2float(h));
}
__device__ __forceinline__ uint32_t pack2h(__half a, __half b){
    __half2 t; t.x = a; t.y = b;
    return *reinterpret_cast<uint32_t*>(&t);
}

// ------------------------- sync helpers ------------------------------------
__device__ __forceinline__ void flag_inc(int* f){
    __syncthreads();
    __threadfence();
    if (threadIdx.x == 0)
        asm volatile("red.release.gpu.global.add.s32 [%0], 1;" :: "l"(f) : "memory");
}
__device__ __forceinline__ void flag_wait(int* f, int thr){   // CTA-wide (phase0 only)
    if (threadIdx.x == 0){
        int v;
        do {
            asm volatile("ld.acquire.gpu.global.s32 %0, [%1];" : "=r"(v) : "l"(f));
            if (v < thr) __nanosleep(128);
        } while (v < thr);
    }
    __syncthreads();
}
__device__ __forceinline__ void prod_wait(int* f, int thr){   // producer warps only
    if (threadIdx.x == 256){
        int v;
        do {
            asm volatile("ld.acquire.gpu.global.s32 %0, [%1];" : "=r"(v) : "l"(f));
            if (v < thr) __nanosleep(128);
        } while (v < thr);
    }
    asm volatile("bar.sync 2, 128;" ::: "memory");
}

__device__ __forceinline__ uint32_t smem_u32(const void* p){
    uint32_t a;
    asm("{ .reg .u64 t; cvta.to.shared.u64 t, %1; cvt.u32.u64 %0, t; }" : "=r"(a) : "l"(p));
    return a;
}
#define MBAR_INIT(mb, c)  asm volatile("mbarrier.init.shared.b64 [%0], %1;" :: "r"(mb), "r"(c) : "memory")
#define MBAR_ARRIVE(mb)   asm volatile("mbarrier.arrive.shared.b64 _, [%0];" :: "r"(mb) : "memory")
__device__ __forceinline__ void mbar_wait(uint32_t mb, uint32_t parity){
    asm volatile(
        "{\n\t.reg .pred P;\n\t"
        "W%=:\n\t"
        "mbarrier.try_wait.parity.acquire.cta.shared::cta.b64 P, [%0], %1, 0x989680;\n\t"
        "@!P bra W%=;\n\t}"
        :: "r"(mb), "r"(parity) : "memory");
}

__device__ __forceinline__ void cpa16(uint32_t dst, const void* src){
    asm volatile("cp.async.cg.shared.global [%0], [%1], 16;" :: "r"(dst), "l"(src) : "memory");
}
#define CPA_COMMIT() asm volatile("cp.async.commit_group;" ::: "memory")
#define CPA_WAIT0()  asm volatile("cp.async.wait_group 0;" ::: "memory")

// ------------------------- mma helpers --------------------------------------
__device__ __forceinline__ void ldsm4(uint32_t* r, const void* p){
    uint32_t a = smem_u32(p);
    asm volatile("ldmatrix.sync.aligned.m8n8.x4.shared.b16 {%0,%1,%2,%3}, [%4];"
        : "=r"(r[0]), "=r"(r[1]), "=r"(r[2]), "=r"(r[3]) : "r"(a));
}
__device__ __forceinline__ void ldsm4t(uint32_t* r, const void* p){
    uint32_t a = smem_u32(p);
    asm volatile("ldmatrix.sync.aligned.m8n8.x4.trans.shared.b16 {%0,%1,%2,%3}, [%4];"
        : "=r"(r[0]), "=r"(r[1]), "=r"(r[2]), "=r"(r[3]) : "r"(a));
}
__device__ __forceinline__ void mma_f16(float* c, const uint32_t* a, const uint32_t* b){
    asm volatile("mma.sync.aligned.m16n8k16.row.col.f32.f16.f16.f32 "
        "{%0,%1,%2,%3}, {%4,%5,%6,%7}, {%8,%9}, {%0,%1,%2,%3};"
        : "+f"(c[0]), "+f"(c[1]), "+f"(c[2]), "+f"(c[3])
        : "r"(a[0]), "r"(a[1]), "r"(a[2]), "r"(a[3]), "r"(b[0]), "r"(b[1]));
}

// ------------------------- phase-0 jobs -------------------------------------
// U[k,r,s] = sum_t B[k,r,t] * W[(k*768+s), t]   — 384-thread job, 48 s-cols
__device__ void p0U_job(int k, int s0, char* smem,
                        const float* __restrict__ B, const float* __restrict__ W){
    float* Bt = (float*)smem;          // [64][65]
    float* Wt = Bt + 64*65;            // [48][65]
    int tid = threadIdx.x;
    int r = tid & 63, sb = tid >> 6;   // sb 0..5
    float acc[8] = {};
    for (int t0 = 0; t0 < DS; t0 += 64){
        __syncthreads();
        #pragma unroll
        for (int i = 0; i < 11; i++){
            int idx = tid + i*384;
            if (idx < 4096){
                int rr = idx >> 6, t = idx & 63;
                Bt[rr*65 + t] = B[(k*64 + rr)*DS + t0 + t];
            }
        }
        #pragma unroll
        for (int i = 0; i < 8; i++){
            int idx = tid + i*384;
            int s = idx >> 6, t = idx & 63;
            Wt[s*65 + t] = W[(size_t)(k*DS + s0 + s)*DS + t0 + t];
        }
        __syncthreads();
        #pragma unroll 8
        for (int t = 0; t < 64; t++){
            float a0 = Bt[r*65 + t];
            #pragma unroll
            for (int j = 0; j < 8; j++)
                acc[j] += a0 * Wt[(sb*8 + j)*65 + t];
        }
    }
    #pragma unroll
    for (int j = 0; j < 8; j++)
        g_U[(k*64 + r)*DS + s0 + sb*8 + j] = acc[j];
}

// Vp[k,sc,r,q] = sum_{s in chunk sc} U[k,r,s] * B[k,q,s]   (256 active threads)
__device__ void p0V_job(int k, int sc, char* smem, const float* __restrict__ B){
    float* Us = (float*)smem;          // [64][65]
    float* Bs = Us + 64*65;
    int tid = threadIdx.x;
    float acc[4][4] = {};
    int r0 = (tid & 15)*4, q0 = ((tid >> 4) & 15)*4;
    for (int si = 0; si < 3; si++){
        int s0 = sc*192 + si*64;
        __syncthreads();
        if (tid < 256){
            #pragma unroll
            for (int i = 0; i < 16; i++){
                int idx = tid + (i<<8); int r = idx>>6, s = idx&63;
                Us[r*65 + s] = g_U[(k*64 + r)*DS + s0 + s];
                Bs[r*65 + s] = B[(k*64 + r)*DS + s0 + s];
            }
        }
        __syncthreads();
        if (tid < 256){
            #pragma unroll 4
            for (int s = 0; s < 64; s++){
                float a[4], b[4];
                #pragma unroll
                for (int i = 0; i < 4; i++){ a[i] = Us[(r0+i)*65 + s]; b[i] = Bs[(q0+i)*65 + s]; }
                #pragma unroll
                for (int i = 0; i < 4; i++)
                    #pragma unroll
                    for (int j = 0; j < 4; j++) acc[i][j] += a[i]*b[j];
            }
        }
    }
    if (tid < 256)
        #pragma unroll
        for (int i = 0; i < 4; i++)
            #pragma unroll
            for (int j = 0; j < 4; j++)
                g_Vp[((k*4 + sc)*64 + r0 + i)*64 + q0 + j] = acc[i][j];
}

// G[k,r,e] = sum_q V[k,r,q] * A[k,e,q]; writes fp16 directly (256 active)
__device__ void p0G_job(int k, int e0, char* smem, const float* __restrict__ A){
    float* Vs = (float*)smem;          // [64][68]
    float* As = Vs + 64*68;
    int tid = threadIdx.x;
    __syncthreads();
    if (tid < 256){
        #pragma unroll
        for (int i = 0; i < 16; i++){
            int idx = tid + (i<<8); int a = idx>>6, b = idx&63;
            float v = 0.f;
            #pragma unroll
            for (int sc = 0; sc < 4; sc++) v += g_Vp[((k*4 + sc)*64 + a)*64 + b];
            Vs[a*68 + b] = v;
            As[a*68 + b] = A[(size_t)(k*DL + e0 + a)*RK + b];
        }
    }
    __syncthreads();
    if (tid < 256){
        int r0 = (tid & 15)*4, ee = ((tid >> 4) & 15)*4;
        float acc[4][4] = {};
        #pragma unroll 4
        for (int q = 0; q < 64; q++){
            float a[4], b[4];
            #pragma unroll
            for (int i = 0; i < 4; i++){ a[i] = Vs[(r0+i)*68 + q]; b[i] = As[(ee+i)*68 + q]; }
            #pragma unroll
            for (int i = 0; i < 4; i++)
                #pragma unroll
                for (int j = 0; j < 4; j++) acc[i][j] += a[i]*b[j];
        }
        #pragma unroll
        for (int i = 0; i < 4; i++)
            #pragma unroll
            for (int j = 0; j < 4; j++)
                g_G[(size_t)(k*64 + r0 + i)*DL + e0 + ee + j] = __float2half(acc[i][j]);
    }
}

__device__ void phase0(char* smem, const float* __restrict__ W,
                       const float* __restrict__ A, const float* __restrict__ B){
    const int p = blockIdx.x - NWORK;   // 0..39
    const int tid = threadIdx.x;

    for (int idx = p*NTHR + tid; idx < K3*DL*RK; idx += NP0*NTHR){
        int k = idx/(DL*RK); int rem = idx%(DL*RK); int d = rem/RK; int r = rem%RK;
        g_Af[d*NJ + k*RK + r] = __float2half(A[idx]);
    }
    flag_inc(&c_A);

    // U: 48 jobs of (k, 48 cols)
    for (int j = p; j < 48; j += NP0)
        p0U_job(j/16, (j%16)*48, smem, B, W);
    flag_inc(&c_U);
    flag_wait(&c_U, NP0);

    // V: 12 jobs
    if (p < 12){
        p0V_job(p/4, p%4, smem, B);
        flag_inc(&c_V);
    }
    flag_wait(&c_V, 12);

    // G: 48 jobs
    for (int j = p; j < 48; j += NP0)
        p0G_job(j/16, (j%16)*64, smem, A);
    flag_inc(&c_G);
}

// ------------------------- worker smem layout (64-row tiles) ----------------
// x bufs  [s][hl] 2x2x9216  @ 0       (end 36864)
// A bufs  [s]     2x25600   @ 36864   (end 88064)
// t1 hi/lo        2x25600   @ 0       (aliases x + A0 head, stage 2)
// G bufs  [s]     3x17408   @ 51200   (end 103424; overlaps dead A region)
#define XOFF(s,hl)  ((s)*18432 + (hl)*9216)
#define AOFF(s)     (36864 + (s)*25600)
#define T1H_OFF 0
#define T1L_OFF 25600
#define GOFF(s)     (51200 + (s)*17408)
#define SMEM_BYTES  103424
#define XPITCH 72
#define APITCH 200
#define TPITCH 200
#define GPITCH 136

__global__ __launch_bounds__(NTHR, 2)
void qkv_main(const float* __restrict__ x, const float* __restrict__ W,
              const float* __restrict__ A, const float* __restrict__ B,
              float* __restrict__ out){
    extern __shared__ char smem[];
    __shared__ __align__(8) uint64_t s_mb[10];  // f1[2] e1[2] f2[3] e2[3]

    if (blockIdx.x >= NWORK){
        phase0(smem, W, A, B);
        return;
    }

    const int tid = threadIdx.x;
    const uint32_t sbase = smem_u32(smem);
    const uint32_t f1 = smem_u32(&s_mb[0]);
    const uint32_t e1 = smem_u32(&s_mb[2]);
    const uint32_t f2 = smem_u32(&s_mb[4]);
    const uint32_t e2 = smem_u32(&s_mb[7]);
    const int row0 = blockIdx.x * 64;

    if (tid == 0){
        MBAR_INIT(f1,     128); MBAR_INIT(f1 + 8, 128);
        MBAR_INIT(e1,     256); MBAR_INIT(e1 + 8, 256);
        MBAR_INIT(f2,     128); MBAR_INIT(f2 + 8, 128); MBAR_INIT(f2 + 16, 128);
        MBAR_INIT(e2,     256); MBAR_INIT(e2 + 8, 256); MBAR_INIT(e2 + 16, 256);
    }
    __syncthreads();

    if (tid >= 256){
        // ==================== PRODUCER (warps 8-11) ========================
        const int tp = tid - 256;
        prod_wait(&c_A, NP0);
        for (int ci = 0; ci < 16; ci++){
            const int s = ci & 1;
            const uint32_t ph = (ci >> 1) & 1;
            mbar_wait(e1 + s*8, ph ^ 1);
            // A chunk via cp.async (24KB, pre-converted fp16)
            {
                const char* src = (const char*)g_Af + (size_t)ci*24576;
                uint32_t dst = sbase + AOFF(s);
                #pragma unroll
                for (int i = 0; i < 12; i++){
                    int j = tp + (i << 7);
                    int r = j / 24, c = j % 24;
                    cpa16(dst + r*400 + c*16, src + j*16);
                }
                CPA_COMMIT();
            }
            // x chunk (64 rows x 64 cols): LDG -> fp16 hi/lo split -> STS
            {
                const int d0 = ci << 6;
                char* xh = smem + XOFF(s,0);
                char* xl = smem + XOFF(s,1);
                #pragma unroll
                for (int i = 0; i < 8; i++){
                    int idx = tp + (i << 7);
                    int r = idx >> 4, c4 = idx & 15;
                    float4 v = *(const float4*)(x + (size_t)(row0 + r)*DL + d0 + (c4 << 2));
                    __half h0,h1,h2,h3,l0,l1,l2,l3;
                    splith(v.x,h0,l0); splith(v.y,h1,l1);
                    splith(v.z,h2,l2); splith(v.w,h3,l3);
                    uint2 ph2; ph2.x = pack2h(h0,h1); ph2.y = pack2h(h2,h3);
                    uint2 pl2; pl2.x = pack2h(l0,l1); pl2.y = pack2h(l2,l3);
                    *(uint2*)(xh + r*(XPITCH*2) + (c4 << 3)) = ph2;
                    *(uint2*)(xl + r*(XPITCH*2) + (c4 << 3)) = pl2;
                }
            }
            CPA_WAIT0();
            MBAR_ARRIVE(f1 + s*8);
        }
        prod_wait(&c_G, NP0);
        __syncthreads();                       // stage transition
        for (int t = 0; t < 24; t++){
            const int s = t % 3;
            const uint32_t ph = (uint32_t)((t / 3) & 1);
            mbar_wait(e2 + s*8, ph ^ 1);
            const int kq = t >> 3, nt = t & 7;
            const int e0 = nt << 7;
            uint32_t dst = sbase + GOFF(s);
            #pragma unroll
            for (int i = 0; i < 8; i++){
                int j = tp + (i << 7);
                int r = j >> 4, c = j & 15;
                cpa16(dst + r*272 + c*16,
                      (const char*)g_G + ((size_t)(kq*64 + r)*DL + e0)*2 + c*16);
            }
            CPA_COMMIT();
            CPA_WAIT0();
            MBAR_ARRIVE(f2 + s*8);
        }
        return;
    }

    // ======================= CONSUMER (warps 0-7) ==========================
    const int warp = tid >> 5, lane = tid & 31;
    const int wm = warp >> 1, wn = warp & 1;   // 4M(16 rows) x 2N warp grid
    const int lrow = lane & 15;
    const int lcol = (lane >> 4) << 3;

    __half* t1h = (__half*)(smem + T1H_OFF);
    __half* t1l = (__half*)(smem + T1L_OFF);

    float acc[12][4];
    #pragma unroll
    for (int j = 0; j < 12; j++)
        #pragma unroll
        for (int q = 0; q < 4; q++) acc[j][q] = 0.f;

    for (int ci = 0; ci < 16; ci++){
        const int s = ci & 1;
        const uint32_t ph = (ci >> 1) & 1;
        mbar_wait(f1 + s*8, ph);

        __half* xh = (__half*)(smem + XOFF(s,0));
        __half* xl = (__half*)(smem + XOFF(s,1));
        __half* As = (__half*)(smem + AOFF(s));
        #pragma unroll
        for (int ks = 0; ks < 4; ks++){
            uint32_t ah[4], al[4];
            {
                int off = (wm*16 + lrow)*XPITCH + ks*16 + lcol;
                ldsm4(ah, xh + off);
                ldsm4(al, xl + off);
            }
            uint32_t g[6][4];
            #pragma unroll
            for (int pp = 0; pp < 6; pp++){
                int off = (ks*16 + lrow)*APITCH + wn*96 + pp*16 + lcol;
                ldsm4t(g[pp], As + off);
            }
            #pragma unroll
            for (int pp = 0; pp < 6; pp++){
                mma_f16(acc[2*pp],   ah, g[pp]);
                mma_f16(acc[2*pp+1], ah, g[pp] + 2);
            }
            #pragma unroll
            for (int pp = 0; pp < 6; pp++){
                mma_f16(acc[2*pp],   al, g[pp]);
                mma_f16(acc[2*pp+1], al, g[pp] + 2);
            }
        }
        MBAR_ARRIVE(e1 + s*8);
    }

    // consumers done reading x/A buf0-head before t1 overwrite
    asm volatile("bar.sync 1, 256;" ::: "memory");

    // spill t1 (fp16 hi/lo) into [0,51200)
    {
        int r0w = wm*16 + (lane >> 2);
        #pragma unroll
        for (int nt = 0; nt < 12; nt++){
            int c0 = wn*96 + nt*8 + ((lane & 3) << 1);
            __half h0,h1,l0,l1;
            splith(acc[nt][0], h0, l0); splith(acc[nt][1], h1, l1);
            *(uint32_t*)(t1h + r0w*TPITCH + c0) = pack2h(h0,h1);
            *(uint32_t*)(t1l + r0w*TPITCH + c0) = pack2h(l0,l1);
            splith(acc[nt][2], h0, l0); splith(acc[nt][3], h1, l1);
            *(uint32_t*)(t1h + (r0w+8)*TPITCH + c0) = pack2h(h0,h1);
            *(uint32_t*)(t1l + (r0w+8)*TPITCH + c0) = pack2h(l0,l1);
        }
    }
    __syncthreads();                           // stage transition (with producers)

    float acc2[8][4];
    for (int t = 0; t < 24; t++){
        const int s = t % 3;
        const uint32_t ph = (uint32_t)((t / 3) & 1);
        const int kq = t >> 3, nt = t & 7;
        mbar_wait(f2 + s*8, ph);

        #pragma unroll
        for (int j = 0; j < 8; j++)
            #pragma unroll
            for (int q = 0; q < 4; q++) acc2[j][q] = 0.f;

        __half* Gs = (__half*)(smem + GOFF(s));
        #pragma unroll
        for (int ks = 0; ks < 4; ks++){
            uint32_t th[4], tl[4];
            {
                int off = (wm*16 + lrow)*TPITCH + kq*64 + ks*16 + lcol;
                ldsm4(th, t1h + off);
                ldsm4(tl, t1l + off);
            }
            uint32_t g2[4][4];
            #pragma unroll
            for (int pp = 0; pp < 4; pp++){
                int off = (ks*16 + lrow)*GPITCH + wn*64 + pp*16 + lcol;
                ldsm4t(g2[pp], Gs + off);
            }
            #pragma unroll
            for (int pp = 0; pp < 4; pp++){
                mma_f16(acc2[2*pp],   th, g2[pp]);
                mma_f16(acc2[2*pp+1], th, g2[pp] + 2);
            }
            #pragma unroll
            for (int pp = 0; pp < 4; pp++){
                mma_f16(acc2[2*pp],   tl, g2[pp]);
                mma_f16(acc2[2*pp+1], tl, g2[pp] + 2);
            }
        }
        MBAR_ARRIVE(e2 + s*8);

        // epilogue: fp32 stores
        const int e0 = nt << 7;
        {
            int rr = row0 + wm*16 + (lane >> 2);
            int cb = kq*1024 + e0 + wn*64 + ((lane & 3) << 1);
            #pragma unroll
            for (int ntt = 0; ntt < 8; ntt++){
                float2 v01 = make_float2(acc2[ntt][0], acc2[ntt][1]);
                float2 v23 = make_float2(acc2[ntt][2], acc2[ntt][3]);
                *(float2*)(out + (size_t)rr*DOUT + cb + ntt*8)       = v01;
                *(float2*)(out + (size_t)(rr + 8)*DOUT + cb + ntt*8) = v23;
            }
        }
    }
}

// ------------------------- launch ------------------------------------------
extern "C" void kernel_launch(void* const* d_in, const int* in_sizes, int n_in,
                              void* d_out, int out_size){
    const float* x = (const float*)d_in[0];
    const float* W = (const float*)d_in[1];
    const float* A = (const float*)d_in[2];
    const float* B = (const float*)d_in[3];
    for (int i = 0; i < n_in; i++){
        switch (in_sizes[i]){
            case 16777216: x = (const float*)d_in[i]; break;   // [2,8192,1024]
            case 1769472:  W = (const float*)d_in[i]; break;   // [2304,768]
            case 196608:   A = (const float*)d_in[i]; break;   // [3,1024,64]
            case 147456:   B = (const float*)d_in[i]; break;   // [3,64,768]
            default: break;
        }
    }
    float* out = (float*)d_out;

    cudaFuncSetAttribute(qkv_main, cudaFuncAttributeMaxDynamicSharedMemorySize, SMEM_BYTES);
    qkv_main<<<NWORK + NP0, NTHR, SMEM_BYTES>>>(x, W, A, B, out);
}

// round 13
// speedup vs baseline: 1.0459x; 1.0459x over previous
#include <cuda_runtime.h>
#include <cuda_fp16.h>
#include <cstdint>

// ---------------------------------------------------------------------------
// QKVProjectedLinear, single-launch, warp-specialized, SINGLE-PRODUCT fp16:
//   G_k = (B_k Ws_k^T B_k^T) A_k^T  [64,1024]   (phase-0 CTAs 128..147)
//   t1  = fp16(x) @ fp16(A_all)     [16384,192] (stage 1)
//   out_k = fp16(t1_k) @ fp16(G_k)              (stage 2)
// 148 CTAs x 384 thr: 128 workers (128-row tiles), 20 phase-0.
// Worker: warps 0-7 consumers (4Mx2N HMMA), warps 8-11 producers.
// mbarrier rings: x/A depth 2 (stage 1), G depth 3 (stage 2).
// ---------------------------------------------------------------------------

#define K3 3
#define DL 1024
#define DS 768
#define RK 64
#define NJ 192
#define DOUT 3072
#define NWORK 128
#define NP0 20
#define NTHR 384

// ------------------------- device scratch ----------------------------------
__device__ __align__(16) float g_U[K3*RK*DS];
__device__ __align__(16) float g_Vp[K3*4*RK*RK];
__device__ __align__(16) __half g_Af[DL*NJ];             // A_all fp16 [1024,192]
__device__ __align__(16) __half g_G[K3*RK*DL];           // G fp16 [3,64,1024]
__device__ int c_A, c_U, c_V, c_G;

__device__ __forceinline__ uint32_t pack2h(__half a, __half b){
    __half2 t; t.x = a; t.y = b;
    return *reinterpret_cast<uint32_t*>(&t);
}

// ------------------------- sync helpers ------------------------------------
__device__ __forceinline__ void flag_inc(int* f){
    __syncthreads();
    __threadfence();
    if (threadIdx.x == 0)
        asm volatile("red.release.gpu.global.add.s32 [%0], 1;" :: "l"(f) : "memory");
}
__device__ __forceinline__ void flag_wait(int* f, int thr){   // CTA-wide (phase0 only)
    if (threadIdx.x == 0){
        int v;
        do {
            asm volatile("ld.acquire.gpu.global.s32 %0, [%1];" : "=r"(v) : "l"(f));
            if (v < thr) __nanosleep(128);
        } while (v < thr);
    }
    __syncthreads();
}
__device__ __forceinline__ void prod_wait(int* f, int thr){   // producer warps only
    if (threadIdx.x == 256){
        int v;
        do {
            asm volatile("ld.acquire.gpu.global.s32 %0, [%1];" : "=r"(v) : "l"(f));
            if (v < thr) __nanosleep(128);
        } while (v < thr);
    }
    asm volatile("bar.sync 2, 128;" ::: "memory");
}

__device__ __forceinline__ uint32_t smem_u32(const void* p){
    uint32_t a;
    asm("{ .reg .u64 t; cvta.to.shared.u64 t, %1; cvt.u32.u64 %0, t; }" : "=r"(a) : "l"(p));
    return a;
}
#define MBAR_INIT(mb, c)  asm volatile("mbarrier.init.shared.b64 [%0], %1;" :: "r"(mb), "r"(c) : "memory")
#define MBAR_ARRIVE(mb)   asm volatile("mbarrier.arrive.shared.b64 _, [%0];" :: "r"(mb) : "memory")
__device__ __forceinline__ void mbar_wait(uint32_t mb, uint32_t parity){
    asm volatile(
        "{\n\t.reg .pred P;\n\t"
        "W%=:\n\t"
        "mbarrier.try_wait.parity.acquire.cta.shared::cta.b64 P, [%0], %1, 0x989680;\n\t"
        "@!P bra W%=;\n\t}"
        :: "r"(mb), "r"(parity) : "memory");
}

__device__ __forceinline__ void cpa16(uint32_t dst, const void* src){
    asm volatile("cp.async.cg.shared.global [%0], [%1], 16;" :: "r"(dst), "l"(src) : "memory");
}
#define CPA_COMMIT() asm volatile("cp.async.commit_group;" ::: "memory")
#define CPA_WAIT0()  asm volatile("cp.async.wait_group 0;" ::: "memory")

// ------------------------- mma helpers --------------------------------------
__device__ __forceinline__ void ldsm4(uint32_t* r, const void* p){
    uint32_t a = smem_u32(p);
    asm volatile("ldmatrix.sync.aligned.m8n8.x4.shared.b16 {%0,%1,%2,%3}, [%4];"
        : "=r"(r[0]), "=r"(r[1]), "=r"(r[2]), "=r"(r[3]) : "r"(a));
}
__device__ __forceinline__ void ldsm4t(uint32_t* r, const void* p){
    uint32_t a = smem_u32(p);
    asm volatile("ldmatrix.sync.aligned.m8n8.x4.trans.shared.b16 {%0,%1,%2,%3}, [%4];"
        : "=r"(r[0]), "=r"(r[1]), "=r"(r[2]), "=r"(r[3]) : "r"(a));
}
__device__ __forceinline__ void mma_f16(float* c, const uint32_t* a, const uint32_t* b){
    asm volatile("mma.sync.aligned.m16n8k16.row.col.f32.f16.f16.f32 "
        "{%0,%1,%2,%3}, {%4,%5,%6,%7}, {%8,%9}, {%0,%1,%2,%3};"
        : "+f"(c[0]), "+f"(c[1]), "+f"(c[2]), "+f"(c[3])
        : "r"(a[0]), "r"(a[1]), "r"(a[2]), "r"(a[3]), "r"(b[0]), "r"(b[1]));
}

// ------------------------- phase-0 jobs (384-thr CTAs, 256 compute) ---------
__device__ void p0U_job(int k, int s0, char* smem,
                        const float* __restrict__ B, const float* __restrict__ W){
    float* Bt = (float*)smem;          // [64][65]
    float* Wt = Bt + 64*65;            // [32][65]
    int tid = threadIdx.x;
    float acc[2][4] = {};
    int r0 = (tid & 31)*2, sq = ((tid >> 5) & 7)*4;
    for (int t0 = 0; t0 < DS; t0 += 64){
        __syncthreads();
        if (tid < 256){
            #pragma unroll
            for (int i = 0; i < 16; i++){
                int idx = tid + (i<<8); int r = idx>>6, t = idx&63;
                Bt[r*65 + t] = B[(k*64 + r)*DS + t0 + t];
            }
            #pragma unroll
            for (int i = 0; i < 8; i++){
                int idx = tid + (i<<8); int s = idx>>6, t = idx&63;
                Wt[s*65 + t] = W[(size_t)(k*DS + s0 + s)*DS + t0 + t];
            }
        }
        __syncthreads();
        if (tid < 256){
            #pragma unroll 8
            for (int t = 0; t < 64; t++){
                float a0 = Bt[r0*65 + t], a1 = Bt[(r0+1)*65 + t];
                #pragma unroll
                for (int j = 0; j < 4; j++){
                    float b = Wt[(sq+j)*65 + t];
                    acc[0][j] += a0*b;
                    acc[1][j] += a1*b;
                }
            }
        }
    }
    if (tid < 256)
        #pragma unroll
        for (int i = 0; i < 2; i++)
            #pragma unroll
            for (int j = 0; j < 4; j++)
                g_U[(k*64 + r0 + i)*DS + s0 + sq + j] = acc[i][j];
}

__device__ void p0V_job(int k, int sc, char* smem, const float* __restrict__ B){
    float* Us = (float*)smem;          // [64][65]
    float* Bs = Us + 64*65;
    int tid = threadIdx.x;
    float acc[4][4] = {};
    int r0 = (tid & 15)*4, q0 = ((tid >> 4) & 15)*4;
    for (int si = 0; si < 3; si++){
        int s0 = sc*192 + si*64;
        __syncthreads();
        if (tid < 256){
            #pragma unroll
            for (int i = 0; i < 16; i++){
                int idx = tid + (i<<8); int r = idx>>6, s = idx&63;
                Us[r*65 + s] = g_U[(k*64 + r)*DS + s0 + s];
                Bs[r*65 + s] = B[(k*64 + r)*DS + s0 + s];
            }
        }
        __syncthreads();
        if (tid < 256){
            #pragma unroll 4
            for (int s = 0; s < 64; s++){
                float a[4], b[4];
                #pragma unroll
                for (int i = 0; i < 4; i++){ a[i] = Us[(r0+i)*65 + s]; b[i] = Bs[(q0+i)*65 + s]; }
                #pragma unroll
                for (int i = 0; i < 4; i++)
                    #pragma unroll
                    for (int j = 0; j < 4; j++) acc[i][j] += a[i]*b[j];
            }
        }
    }
    if (tid < 256)
        #pragma unroll
        for (int i = 0; i < 4; i++)
            #pragma unroll
            for (int j = 0; j < 4; j++)
                g_Vp[((k*4 + sc)*64 + r0 + i)*64 + q0 + j] = acc[i][j];
}

__device__ void p0G_job(int k, int e0, char* smem, const float* __restrict__ A){
    float* Vs = (float*)smem;          // [64][68]
    float* As = Vs + 64*68;
    int tid = threadIdx.x;
    __syncthreads();
    if (tid < 256){
        #pragma unroll
        for (int i = 0; i < 16; i++){
            int idx = tid + (i<<8); int a = idx>>6, b = idx&63;
            float v = 0.f;
            #pragma unroll
            for (int sc = 0; sc < 4; sc++) v += g_Vp[((k*4 + sc)*64 + a)*64 + b];
            Vs[a*68 + b] = v;
            As[a*68 + b] = A[(size_t)(k*DL + e0 + a)*RK + b];
        }
    }
    __syncthreads();
    if (tid < 256){
        int r0 = (tid & 15)*4, ee = ((tid >> 4) & 15)*4;
        float acc[4][4] = {};
        #pragma unroll 4
        for (int q = 0; q < 64; q++){
            float a[4], b[4];
            #pragma unroll
            for (int i = 0; i < 4; i++){ a[i] = Vs[(r0+i)*68 + q]; b[i] = As[(ee+i)*68 + q]; }
            #pragma unroll
            for (int i = 0; i < 4; i++)
                #pragma unroll
                for (int j = 0; j < 4; j++) acc[i][j] += a[i]*b[j];
        }
        #pragma unroll
        for (int i = 0; i < 4; i++)
            #pragma unroll
            for (int j = 0; j < 4; j++)
                g_G[(size_t)(k*64 + r0 + i)*DL + e0 + ee + j] = __float2half(acc[i][j]);
    }
}

__device__ void phase0(char* smem, const float* __restrict__ W,
                       const float* __restrict__ A, const float* __restrict__ B){
    const int p = blockIdx.x - NWORK;
    const int tid = threadIdx.x;

    for (int idx = p*NTHR + tid; idx < K3*DL*RK; idx += NP0*NTHR){
        int k = idx/(DL*RK); int rem = idx%(DL*RK); int d = rem/RK; int r = rem%RK;
        g_Af[d*NJ + k*RK + r] = __float2half(A[idx]);
    }
    flag_inc(&c_A);

    for (int j = p; j < 72; j += NP0)
        p0U_job(j/24, (j%24)*32, smem, B, W);
    flag_inc(&c_U);
    flag_wait(&c_U, NP0);

    if (p < 12){
        p0V_job(p/4, p%4, smem, B);
        flag_inc(&c_V);
    }
    flag_wait(&c_V, 12);

    for (int j = p; j < 48; j += NP0)
        p0G_job(j/16, (j%16)*64, smem, A);
    flag_inc(&c_G);
}

// ------------------------- worker smem layout (single fp16) -----------------
// x bufs [s] 2 x 18432 @ 0        (end 36864)
// A bufs [s] 2 x 25600 @ 36864    (end 88064)
// t1 (single) 51200 @ 0           (aliases x + A0 head, stage 2)
// G bufs [s] 3 x 17408 @ 51200    (end 103424; overlaps dead A tail, filled
//                                  only after the stage-transition barrier)
#define XOFF(s)     ((s)*18432)
#define AOFF(s)     (36864 + (s)*25600)
#define T1_OFF      0
#define GOFF(s)     (51200 + (s)*17408)
#define SMEM_BYTES  103424
#define XPITCH 72
#define APITCH 200
#define TPITCH 200
#define GPITCH 136

__global__ __launch_bounds__(NTHR, 1)
void qkv_main(const float* __restrict__ x, const float* __restrict__ W,
              const float* __restrict__ A, const float* __restrict__ B,
              float* __restrict__ out){
    extern __shared__ char smem[];
    __shared__ __align__(8) uint64_t s_mb[10];  // f1[2] e1[2] f2[3] e2[3]

    if (blockIdx.x >= NWORK){
        phase0(smem, W, A, B);
        return;
    }

    const int tid = threadIdx.x;
    const uint32_t sbase = smem_u32(smem);
    const uint32_t f1 = smem_u32(&s_mb[0]);
    const uint32_t e1 = smem_u32(&s_mb[2]);
    const uint32_t f2 = smem_u32(&s_mb[4]);
    const uint32_t e2 = smem_u32(&s_mb[7]);
    const int row0 = blockIdx.x * 128;

    if (tid == 0){
        MBAR_INIT(f1,     128); MBAR_INIT(f1 + 8, 128);
        MBAR_INIT(e1,     256); MBAR_INIT(e1 + 8, 256);
        MBAR_INIT(f2,     128); MBAR_INIT(f2 + 8, 128); MBAR_INIT(f2 + 16, 128);
        MBAR_INIT(e2,     256); MBAR_INIT(e2 + 8, 256); MBAR_INIT(e2 + 16, 256);
    }
    __syncthreads();

    if (tid >= 256){
        // ==================== PRODUCER (warps 8-11) ========================
        const int tp = tid - 256;
        prod_wait(&c_A, NP0);
        for (int ci = 0; ci < 16; ci++){
            const int s = ci & 1;
            const uint32_t ph = (ci >> 1) & 1;
            mbar_wait(e1 + s*8, ph ^ 1);
            // A chunk via cp.async (24KB, pre-converted fp16)
            {
                const char* src = (const char*)g_Af + (size_t)ci*24576;
                uint32_t dst = sbase + AOFF(s);
                #pragma unroll
                for (int i = 0; i < 12; i++){
                    int j = tp + (i << 7);
                    int r = j / 24, c = j % 24;
                    cpa16(dst + r*400 + c*16, src + j*16);
                }
                CPA_COMMIT();
            }
            // x chunk (128 rows x 64 cols): LDG -> fp16 -> STS (single)
            {
                const int d0 = ci << 6;
                char* xs = smem + XOFF(s);
                #pragma unroll
                for (int i = 0; i < 16; i++){
                    int idx = tp + (i << 7);
                    int r = idx >> 4, c4 = idx & 15;
                    float4 v = *(const float4*)(x + (size_t)(row0 + r)*DL + d0 + (c4 << 2));
                    uint2 p2;
                    p2.x = pack2h(__float2half(v.x), __float2half(v.y));
                    p2.y = pack2h(__float2half(v.z), __float2half(v.w));
                    *(uint2*)(xs + r*(XPITCH*2) + (c4 << 3)) = p2;
                }
            }
            CPA_WAIT0();
            MBAR_ARRIVE(f1 + s*8);
        }
        prod_wait(&c_G, NP0);
        __syncthreads();                       // stage transition
        for (int t = 0; t < 24; t++){
            const int s = t % 3;
            const uint32_t ph = (uint32_t)((t / 3) & 1);
            mbar_wait(e2 + s*8, ph ^ 1);
            const int kq = t >> 3, nt = t & 7;
            const int e0 = nt << 7;
            uint32_t dst = sbase + GOFF(s);
            #pragma unroll
            for (int i = 0; i < 8; i++){
                int j = tp + (i << 7);
                int r = j >> 4, c = j & 15;
                cpa16(dst + r*272 + c*16,
                      (const char*)g_G + ((size_t)(kq*64 + r)*DL + e0)*2 + c*16);
            }
            CPA_COMMIT();
            CPA_WAIT0();
            MBAR_ARRIVE(f2 + s*8);
        }
        return;
    }

    // ======================= CONSUMER (warps 0-7) ==========================
    const int warp = tid >> 5, lane = tid & 31;
    const int wm = warp >> 1, wn = warp & 1;   // 4M(32 rows) x 2N warp grid
    const int lrow = lane & 15;
    const int lcol = (lane >> 4) << 3;

    __half* t1s = (__half*)(smem + T1_OFF);

    float acc[2][12][4];
    #pragma unroll
    for (int i = 0; i < 2; i++)
        #pragma unroll
        for (int j = 0; j < 12; j++)
            #pragma unroll
            for (int q = 0; q < 4; q++) acc[i][j][q] = 0.f;

    for (int ci = 0; ci < 16; ci++){
        const int s = ci & 1;
        const uint32_t ph = (ci >> 1) & 1;
        mbar_wait(f1 + s*8, ph);

        __half* xs = (__half*)(smem + XOFF(s));
        __half* As = (__half*)(smem + AOFF(s));
        #pragma unroll
        for (int ks = 0; ks < 4; ks++){
            uint32_t ah[2][4];
            #pragma unroll
            for (int mt = 0; mt < 2; mt++){
                int off = (wm*32 + mt*16 + lrow)*XPITCH + ks*16 + lcol;
                ldsm4(ah[mt], xs + off);
            }
            uint32_t g[6][4];
            #pragma unroll
            for (int pp = 0; pp < 6; pp++){
                int off = (ks*16 + lrow)*APITCH + wn*96 + pp*16 + lcol;
                ldsm4t(g[pp], As + off);
            }
            #pragma unroll
            for (int pp = 0; pp < 6; pp++)
                #pragma unroll
                for (int mt = 0; mt < 2; mt++){
                    mma_f16(acc[mt][2*pp],   ah[mt], g[pp]);
                    mma_f16(acc[mt][2*pp+1], ah[mt], g[pp] + 2);
                }
        }
        MBAR_ARRIVE(e1 + s*8);
    }

    // consumers done reading x/A before t1 overwrite
    asm volatile("bar.sync 1, 256;" ::: "memory");

    // spill t1 (single fp16) into [0,51200)
    #pragma unroll
    for (int mt = 0; mt < 2; mt++){
        int r0w = wm*32 + mt*16 + (lane >> 2);
        #pragma unroll
        for (int nt = 0; nt < 12; nt++){
            int c0 = wn*96 + nt*8 + ((lane & 3) << 1);
            *(uint32_t*)(t1s + r0w*TPITCH + c0) =
                pack2h(__float2half(acc[mt][nt][0]), __float2half(acc[mt][nt][1]));
            *(uint32_t*)(t1s + (r0w+8)*TPITCH + c0) =
                pack2h(__float2half(acc[mt][nt][2]), __float2half(acc[mt][nt][3]));
        }
    }
    __syncthreads();                           // stage transition (with producers)

    float acc2[2][8][4];
    for (int t = 0; t < 24; t++){
        const int s = t % 3;
        const uint32_t ph = (uint32_t)((t / 3) & 1);
        const int kq = t >> 3, nt = t & 7;
        mbar_wait(f2 + s*8, ph);

        #pragma unroll
        for (int i = 0; i < 2; i++)
            #pragma unroll
            for (int j = 0; j < 8; j++)
                #pragma unroll
                for (int q = 0; q < 4; q++) acc2[i][j][q] = 0.f;

        __half* Gs = (__half*)(smem + GOFF(s));
        #pragma unroll
        for (int ks = 0; ks < 4; ks++){
            uint32_t th[2][4];
            #pragma unroll
            for (int mt = 0; mt < 2; mt++){
                int off = (wm*32 + mt*16 + lrow)*TPITCH + kq*64 + ks*16 + lcol;
                ldsm4(th[mt], t1s + off);
            }
            uint32_t g2[4][4];
            #pragma unroll
            for (int pp = 0; pp < 4; pp++){
                int off = (ks*16 + lrow)*GPITCH + wn*64 + pp*16 + lcol;
                ldsm4t(g2[pp], Gs + off);
            }
            #pragma unroll
            for (int pp = 0; pp < 4; pp++)
                #pragma unroll
                for (int mt = 0; mt < 2; mt++){
                    mma_f16(acc2[mt][2*pp],   th[mt], g2[pp]);
                    mma_f16(acc2[mt][2*pp+1], th[mt], g2[pp] + 2);
                }
        }
        MBAR_ARRIVE(e2 + s*8);

        // epilogue: fp32 stores
        const int e0 = nt << 7;
        #pragma unroll
        for (int mt = 0; mt < 2; mt++){
            int rr = row0 + wm*32 + mt*16 + (lane >> 2);
            int cb = kq*1024 + e0 + wn*64 + ((lane & 3) << 1);
            #pragma unroll
            for (int ntt = 0; ntt < 8; ntt++){
                float2 v01 = make_float2(acc2[mt][ntt][0], acc2[mt][ntt][1]);
                float2 v23 = make_float2(acc2[mt][ntt][2], acc2[mt][ntt][3]);
                *(float2*)(out + (size_t)rr*DOUT + cb + ntt*8)       = v01;
                *(float2*)(out + (size_t)(rr + 8)*DOUT + cb + ntt*8) = v23;
            }
        }
    }
}

// ------------------------- launch ------------------------------------------
extern "C" void kernel_launch(void* const* d_in, const int* in_sizes, int n_in,
                              void* d_out, int out_size){
    const float* x = (const float*)d_in[0];
    const float* W = (const float*)d_in[1];
    const float* A = (const float*)d_in[2];
    const float* B = (const float*)d_in[3];
    for (int i = 0; i < n_in; i++){
        switch (in_sizes[i]){
            case 16777216: x = (const float*)d_in[i]; break;   // [2,8192,1024]
            case 1769472:  W = (const float*)d_in[i]; break;   // [2304,768]
            case 196608:   A = (const float*)d_in[i]; break;   // [3,1024,64]
            case 147456:   B = (const float*)d_in[i]; break;   // [3,64,768]
            default: break;
        }
    }
    float* out = (float*)d_out;

    cudaFuncSetAttribute(qkv_main, cudaFuncAttributeMaxDynamicSharedMemorySize, SMEM_BYTES);
    qkv_main<<<NWORK + NP0, NTHR, SMEM_BYTES>>>(x, W, A, B, out);
}

// round 14
// speedup vs baseline: 1.6868x; 1.6129x over previous
#include <cuda_runtime.h>
#include <cuda_fp16.h>
#include <cstdint>

// ---------------------------------------------------------------------------
// QKVProjectedLinear, single-launch, warp-specialized, SINGLE-PRODUCT fp16.
//   U = B @ Ws^T          : distributed over CTAs 0..143 (64x16 jobs)
//   V = U @ B^T, G = V@A^T: CTAs 128..147 after c_U
//   t1  = fp16(x) @ fp16(A_all)   (stage 1, workers 0..127)
//   out_k = fp16(t1_k) @ fp16(G_k) (stage 2)
// 148 CTAs x 384 thr. Worker: warps 0-7 consumers, 8-11 producers.
// ---------------------------------------------------------------------------

#define K3 3
#define DL 1024
#define DS 768
#define RK 64
#define NJ 192
#define DOUT 3072
#define NWORK 128
#define NCTA 148
#define NU 144
#define NP0 20
#define NTHR 384

// ------------------------- device scratch ----------------------------------
__device__ __align__(16) float g_U[K3*RK*DS];
__device__ __align__(16) float g_Vp[K3*4*RK*RK];
__device__ __align__(16) __half g_Af[DL*NJ];             // A_all fp16 [1024,192]
__device__ __align__(16) __half g_G[K3*RK*DL];           // G fp16 [3,64,1024]
__device__ int c_A, c_U, c_V, c_G;

__device__ __forceinline__ uint32_t pack2h(__half a, __half b){
    __half2 t; t.x = a; t.y = b;
    return *reinterpret_cast<uint32_t*>(&t);
}

// ------------------------- sync helpers ------------------------------------
__device__ __forceinline__ void flag_inc(int* f){
    __syncthreads();
    __threadfence();
    if (threadIdx.x == 0)
        asm volatile("red.release.gpu.global.add.s32 [%0], 1;" :: "l"(f) : "memory");
}
__device__ __forceinline__ void flag_wait(int* f, int thr){   // CTA-wide
    if (threadIdx.x == 0){
        int v;
        do {
            asm volatile("ld.acquire.gpu.global.s32 %0, [%1];" : "=r"(v) : "l"(f));
            if (v < thr) __nanosleep(128);
        } while (v < thr);
    }
    __syncthreads();
}
__device__ __forceinline__ void prod_wait(int* f, int thr){   // producer warps only
    if (threadIdx.x == 256){
        int v;
        do {
            asm volatile("ld.acquire.gpu.global.s32 %0, [%1];" : "=r"(v) : "l"(f));
            if (v < thr) __nanosleep(128);
        } while (v < thr);
    }
    asm volatile("bar.sync 2, 128;" ::: "memory");
}

__device__ __forceinline__ uint32_t smem_u32(const void* p){
    uint32_t a;
    asm("{ .reg .u64 t; cvta.to.shared.u64 t, %1; cvt.u32.u64 %0, t; }" : "=r"(a) : "l"(p));
    return a;
}
#define MBAR_INIT(mb, c)  asm volatile("mbarrier.init.shared.b64 [%0], %1;" :: "r"(mb), "r"(c) : "memory")
#define MBAR_ARRIVE(mb)   asm volatile("mbarrier.arrive.shared.b64 _, [%0];" :: "r"(mb) : "memory")
__device__ __forceinline__ void mbar_wait(uint32_t mb, uint32_t parity){
    asm volatile(
        "{\n\t.reg .pred P;\n\t"
        "W%=:\n\t"
        "mbarrier.try_wait.parity.acquire.cta.shared::cta.b64 P, [%0], %1, 0x989680;\n\t"
        "@!P bra W%=;\n\t}"
        :: "r"(mb), "r"(parity) : "memory");
}

__device__ __forceinline__ void cpa16(uint32_t dst, const void* src){
    asm volatile("cp.async.cg.shared.global [%0], [%1], 16;" :: "r"(dst), "l"(src) : "memory");
}
#define CPA_COMMIT() asm volatile("cp.async.commit_group;" ::: "memory")
#define CPA_WAIT0()  asm volatile("cp.async.wait_group 0;" ::: "memory")

// ------------------------- mma helpers --------------------------------------
__device__ __forceinline__ void ldsm4(uint32_t* r, const void* p){
    uint32_t a = smem_u32(p);
    asm volatile("ldmatrix.sync.aligned.m8n8.x4.shared.b16 {%0,%1,%2,%3}, [%4];"
        : "=r"(r[0]), "=r"(r[1]), "=r"(r[2]), "=r"(r[3]) : "r"(a));
}
__device__ __forceinline__ void ldsm4t(uint32_t* r, const void* p){
    uint32_t a = smem_u32(p);
    asm volatile("ldmatrix.sync.aligned.m8n8.x4.trans.shared.b16 {%0,%1,%2,%3}, [%4];"
        : "=r"(r[0]), "=r"(r[1]), "=r"(r[2]), "=r"(r[3]) : "r"(a));
}
__device__ __forceinline__ void mma_f16(float* c, const uint32_t* a, const uint32_t* b){
    asm volatile("mma.sync.aligned.m16n8k16.row.col.f32.f16.f16.f32 "
        "{%0,%1,%2,%3}, {%4,%5,%6,%7}, {%8,%9}, {%0,%1,%2,%3};"
        : "+f"(c[0]), "+f"(c[1]), "+f"(c[2]), "+f"(c[3])
        : "r"(a[0]), "r"(a[1]), "r"(a[2]), "r"(a[3]), "r"(b[0]), "r"(b[1]));
}

// ------------------------- phase-0 jobs -------------------------------------
// U[k,r,s] = sum_t B[k,r,t]*W[(k*768+s),t].  Job: 64 rows x 16 s-cols.
// Bank-conflict-free: a-loads lane-indexed (stride 65), b-loads warp-uniform
// (broadcast). Compute on warps 0-3 (tid<128), loads by all 384 threads.
__device__ void p0U16_job(int k, int s0, char* smem,
                          const float* __restrict__ B, const float* __restrict__ W){
    float* Bt = (float*)smem;          // [64][65]
    float* Wt = Bt + 64*65;            // [16][65]
    const int tid = threadIdx.x;
    const int lane = tid & 31, w = tid >> 5;
    float acc[2][4] = {};
    for (int tc = 0; tc < 12; tc++){
        const int t0 = tc*64;
        __syncthreads();
        #pragma unroll
        for (int i = 0; i < 11; i++){
            int idx = tid + i*NTHR;
            if (idx < 4096){
                int r = idx >> 6, t = idx & 63;
                Bt[r*65 + t] = B[(k*64 + r)*DS + t0 + t];
            }
        }
        #pragma unroll
        for (int i = 0; i < 3; i++){
            int idx = tid + i*NTHR;
            if (idx < 1024){
                int s = idx >> 6, t = idx & 63;
                Wt[s*65 + t] = W[(size_t)(k*DS + s0 + s)*DS + t0 + t];
            }
        }
        __syncthreads();
        if (w < 4){
            #pragma unroll 8
            for (int t = 0; t < 64; t++){
                float a0 = Bt[lane*65 + t];
                float a1 = Bt[(lane + 32)*65 + t];
                #pragma unroll
                for (int j = 0; j < 4; j++){
                    float b = Wt[(w*4 + j)*65 + t];
                    acc[0][j] += a0*b;
                    acc[1][j] += a1*b;
                }
            }
        }
    }
    if (w < 4){
        #pragma unroll
        for (int j = 0; j < 4; j++){
            g_U[(k*64 + lane)*DS + s0 + w*4 + j]      = acc[0][j];
            g_U[(k*64 + lane + 32)*DS + s0 + w*4 + j] = acc[1][j];
        }
    }
}

// Vp[k,sc,r,q] = sum_{s in chunk sc} U[k,r,s]*B[k,q,s]  (256 active threads)
__device__ void p0V_job(int k, int sc, char* smem, const float* __restrict__ B){
    float* Us = (float*)smem;          // [64][65]
    float* Bs = Us + 64*65;
    int tid = threadIdx.x;
    float acc[4][4] = {};
    int r0 = (tid & 15)*4, q0 = ((tid >> 4) & 15)*4;
    for (int si = 0; si < 3; si++){
        int s0 = sc*192 + si*64;
        __syncthreads();
        if (tid < 256){
            #pragma unroll
            for (int i = 0; i < 16; i++){
                int idx = tid + (i<<8); int r = idx>>6, s = idx&63;
                Us[r*65 + s] = g_U[(k*64 + r)*DS + s0 + s];
                Bs[r*65 + s] = B[(k*64 + r)*DS + s0 + s];
            }
        }
        __syncthreads();
        if (tid < 256){
            #pragma unroll 4
            for (int s = 0; s < 64; s++){
                float a[4], b[4];
                #pragma unroll
                for (int i = 0; i < 4; i++){ a[i] = Us[(r0+i)*65 + s]; b[i] = Bs[(q0+i)*65 + s]; }
                #pragma unroll
                for (int i = 0; i < 4; i++)
                    #pragma unroll
                    for (int j = 0; j < 4; j++) acc[i][j] += a[i]*b[j];
            }
        }
    }
    if (tid < 256)
        #pragma unroll
        for (int i = 0; i < 4; i++)
            #pragma unroll
            for (int j = 0; j < 4; j++)
                g_Vp[((k*4 + sc)*64 + r0 + i)*64 + q0 + j] = acc[i][j];
}

// G[k,r,e] = sum_q V[k,r,q]*A[k,e,q]; writes fp16 directly (256 active)
__device__ void p0G_job(int k, int e0, char* smem, const float* __restrict__ A){
    float* Vs = (float*)smem;          // [64][68]
    float* As = Vs + 64*68;
    int tid = threadIdx.x;
    __syncthreads();
    if (tid < 256){
        #pragma unroll
        for (int i = 0; i < 16; i++){
            int idx = tid + (i<<8); int a = idx>>6, b = idx&63;
            float v = 0.f;
            #pragma unroll
            for (int sc = 0; sc < 4; sc++) v += g_Vp[((k*4 + sc)*64 + a)*64 + b];
            Vs[a*68 + b] = v;
            As[a*68 + b] = A[(size_t)(k*DL + e0 + a)*RK + b];
        }
    }
    __syncthreads();
    if (tid < 256){
        int r0 = (tid & 15)*4, ee = ((tid >> 4) & 15)*4;
        float acc[4][4] = {};
        #pragma unroll 4
        for (int q = 0; q < 64; q++){
            float a[4], b[4];
            #pragma unroll
            for (int i = 0; i < 4; i++){ a[i] = Vs[(r0+i)*68 + q]; b[i] = As[(ee+i)*68 + q]; }
            #pragma unroll
            for (int i = 0; i < 4; i++)
                #pragma unroll
                for (int j = 0; j < 4; j++) acc[i][j] += a[i]*b[j];
        }
        #pragma unroll
        for (int i = 0; i < 4; i++)
            #pragma unroll
            for (int j = 0; j < 4; j++)
                g_G[(size_t)(k*64 + r0 + i)*DL + e0 + ee + j] = __float2half(acc[i][j]);
    }
}

// ------------------------- worker smem layout (single fp16) -----------------
// x bufs [s] 2 x 18432 @ 0        (end 36864)
// A bufs [s] 2 x 25600 @ 36864    (end 88064)
// t1 (single) 51200 @ 0           (aliases x + A0 head, stage 2)
// G bufs [s] 3 x 17408 @ 51200    (end 103424)
// U scratch (phase 0, before pipeline): [64][65]+[16][65] floats = 20.8KB @ 0
#define XOFF(s)     ((s)*18432)
#define AOFF(s)     (36864 + (s)*25600)
#define T1_OFF      0
#define GOFF(s)     (51200 + (s)*17408)
#define SMEM_BYTES  103424
#define XPITCH 72
#define APITCH 200
#define TPITCH 200
#define GPITCH 136

__global__ __launch_bounds__(NTHR, 1)
void qkv_main(const float* __restrict__ x, const float* __restrict__ W,
              const float* __restrict__ A, const float* __restrict__ B,
              float* __restrict__ out){
    extern __shared__ char smem[];
    __shared__ __align__(8) uint64_t s_mb[10];  // f1[2] e1[2] f2[3] e2[3]

    const int tid = threadIdx.x;
    const int bid = blockIdx.x;

    // ===== phase 0a: A conversion (all CTAs) ===============================
    for (int idx = bid*NTHR + tid; idx < K3*DL*RK; idx += NCTA*NTHR){
        int k = idx/(DL*RK); int rem = idx%(DL*RK); int d = rem/RK; int r = rem%RK;
        g_Af[d*NJ + k*RK + r] = __float2half(A[idx]);
    }
    flag_inc(&c_A);

    // ===== phase 0b: U distributed (CTAs 0..143, one 64x16 job each) =======
    if (bid < NU){
        p0U16_job(bid/48, (bid%48)*16, smem, B, W);
        flag_inc(&c_U);
    }

    // ===== phase-0 tail CTAs: V then G =====================================
    if (bid >= NWORK){
        const int p = bid - NWORK;     // 0..19
        flag_wait(&c_U, NU);
        if (p < 12){
            p0V_job(p/4, p%4, smem, B);
            flag_inc(&c_V);
        }
        flag_wait(&c_V, 12);
        for (int j = p; j < 48; j += NP0)
            p0G_job(j/16, (j%16)*64, smem, A);
        flag_inc(&c_G);
        return;
    }

    // ===== workers =========================================================
    const uint32_t sbase = smem_u32(smem);
    const uint32_t f1 = smem_u32(&s_mb[0]);
    const uint32_t e1 = smem_u32(&s_mb[2]);
    const uint32_t f2 = smem_u32(&s_mb[4]);
    const uint32_t e2 = smem_u32(&s_mb[7]);
    const int row0 = bid * 128;

    if (tid == 0){
        MBAR_INIT(f1,     128); MBAR_INIT(f1 + 8, 128);
        MBAR_INIT(e1,     256); MBAR_INIT(e1 + 8, 256);
        MBAR_INIT(f2,     128); MBAR_INIT(f2 + 8, 128); MBAR_INIT(f2 + 16, 128);
        MBAR_INIT(e2,     256); MBAR_INIT(e2 + 8, 256); MBAR_INIT(e2 + 16, 256);
    }
    __syncthreads();

    if (tid >= 256){
        // ==================== PRODUCER (warps 8-11) ========================
        const int tp = tid - 256;
        prod_wait(&c_A, NCTA);
        for (int ci = 0; ci < 16; ci++){
            const int s = ci & 1;
            const uint32_t ph = (ci >> 1) & 1;
            mbar_wait(e1 + s*8, ph ^ 1);
            // A chunk via cp.async (24KB, pre-converted fp16)
            {
                const char* src = (const char*)g_Af + (size_t)ci*24576;
                uint32_t dst = sbase + AOFF(s);
                #pragma unroll
                for (int i = 0; i < 12; i++){
                    int j = tp + (i << 7);
                    int r = j / 24, c = j % 24;
                    cpa16(dst + r*400 + c*16, src + j*16);
                }
                CPA_COMMIT();
            }
            // x chunk (128 rows x 64 cols): LDG -> fp16 -> STS
            {
                const int d0 = ci << 6;
                char* xs = smem + XOFF(s);
                #pragma unroll
                for (int i = 0; i < 16; i++){
                    int idx = tp + (i << 7);
                    int r = idx >> 4, c4 = idx & 15;
                    float4 v = *(const float4*)(x + (size_t)(row0 + r)*DL + d0 + (c4 << 2));
                    uint2 p2;
                    p2.x = pack2h(__float2half(v.x), __float2half(v.y));
                    p2.y = pack2h(__float2half(v.z), __float2half(v.w));
                    *(uint2*)(xs + r*(XPITCH*2) + (c4 << 3)) = p2;
                }
            }
            CPA_WAIT0();
            MBAR_ARRIVE(f1 + s*8);
        }
        prod_wait(&c_G, NP0);
        __syncthreads();                       // stage transition
        for (int t = 0; t < 24; t++){
            const int s = t % 3;
            const uint32_t ph = (uint32_t)((t / 3) & 1);
            mbar_wait(e2 + s*8, ph ^ 1);
            const int kq = t >> 3, nt = t & 7;
            const int e0 = nt << 7;
            uint32_t dst = sbase + GOFF(s);
            #pragma unroll
            for (int i = 0; i < 8; i++){
                int j = tp + (i << 7);
                int r = j >> 4, c = j & 15;
                cpa16(dst + r*272 + c*16,
                      (const char*)g_G + ((size_t)(kq*64 + r)*DL + e0)*2 + c*16);
            }
            CPA_COMMIT();
            CPA_WAIT0();
            MBAR_ARRIVE(f2 + s*8);
        }
        return;
    }

    // ======================= CONSUMER (warps 0-7) ==========================
    const int warp = tid >> 5, lane = tid & 31;
    const int wm = warp >> 1, wn = warp & 1;   // 4M(32 rows) x 2N warp grid
    const int lrow = lane & 15;
    const int lcol = (lane >> 4) << 3;

    __half* t1s = (__half*)(smem + T1_OFF);

    float acc[2][12][4];
    #pragma unroll
    for (int i = 0; i < 2; i++)
        #pragma unroll
        for (int j = 0; j < 12; j++)
            #pragma unroll
            for (int q = 0; q < 4; q++) acc[i][j][q] = 0.f;

    for (int ci = 0; ci < 16; ci++){
        const int s = ci & 1;
        const uint32_t ph = (ci >> 1) & 1;
        mbar_wait(f1 + s*8, ph);

        __half* xs = (__half*)(smem + XOFF(s));
        __half* As = (__half*)(smem + AOFF(s));
        #pragma unroll
        for (int ks = 0; ks < 4; ks++){
            uint32_t ah[2][4];
            #pragma unroll
            for (int mt = 0; mt < 2; mt++){
                int off = (wm*32 + mt*16 + lrow)*XPITCH + ks*16 + lcol;
                ldsm4(ah[mt], xs + off);
            }
            uint32_t g[6][4];
            #pragma unroll
            for (int pp = 0; pp < 6; pp++){
                int off = (ks*16 + lrow)*APITCH + wn*96 + pp*16 + lcol;
                ldsm4t(g[pp], As + off);
            }
            #pragma unroll
            for (int pp = 0; pp < 6; pp++)
                #pragma unroll
                for (int mt = 0; mt < 2; mt++){
                    mma_f16(acc[mt][2*pp],   ah[mt], g[pp]);
                    mma_f16(acc[mt][2*pp+1], ah[mt], g[pp] + 2);
                }
        }
        MBAR_ARRIVE(e1 + s*8);
    }

    // consumers done reading x/A before t1 overwrite
    asm volatile("bar.sync 1, 256;" ::: "memory");

    // spill t1 (single fp16) into [0,51200)
    #pragma unroll
    for (int mt = 0; mt < 2; mt++){
        int r0w = wm*32 + mt*16 + (lane >> 2);
        #pragma unroll
        for (int nt = 0; nt < 12; nt++){
            int c0 = wn*96 + nt*8 + ((lane & 3) << 1);
            *(uint32_t*)(t1s + r0w*TPITCH + c0) =
                pack2h(__float2half(acc[mt][nt][0]), __float2half(acc[mt][nt][1]));
            *(uint32_t*)(t1s + (r0w+8)*TPITCH + c0) =
                pack2h(__float2half(acc[mt][nt][2]), __float2half(acc[mt][nt][3]));
        }
    }
    __syncthreads();                           // stage transition (with producers)

    float acc2[2][8][4];
    for (int t = 0; t < 24; t++){
        const int s = t % 3;
        const uint32_t ph = (uint32_t)((t / 3) & 1);
        const int kq = t >> 3, nt = t & 7;
        mbar_wait(f2 + s*8, ph);

        #pragma unroll
        for (int i = 0; i < 2; i++)
            #pragma unroll
            for (int j = 0; j < 8; j++)
                #pragma unroll
                for (int q = 0; q < 4; q++) acc2[i][j][q] = 0.f;

        __half* Gs = (__half*)(smem + GOFF(s));
        #pragma unroll
        for (int ks = 0; ks < 4; ks++){
            uint32_t th[2][4];
            #pragma unroll
            for (int mt = 0; mt < 2; mt++){
                int off = (wm*32 + mt*16 + lrow)*TPITCH + kq*64 + ks*16 + lcol;
                ldsm4(th[mt], t1s + off);
            }
            uint32_t g2[4][4];
            #pragma unroll
            for (int pp = 0; pp < 4; pp++){
                int off = (ks*16 + lrow)*GPITCH + wn*64 + pp*16 + lcol;
                ldsm4t(g2[pp], Gs + off);
            }
            #pragma unroll
            for (int pp = 0; pp < 4; pp++)
                #pragma unroll
                for (int mt = 0; mt < 2; mt++){
                    mma_f16(acc2[mt][2*pp],   th[mt], g2[pp]);
                    mma_f16(acc2[mt][2*pp+1], th[mt], g2[pp] + 2);
                }
        }
        MBAR_ARRIVE(e2 + s*8);

        // epilogue: fp32 stores
        const int e0 = nt << 7;
        #pragma unroll
        for (int mt = 0; mt < 2; mt++){
            int rr = row0 + wm*32 + mt*16 + (lane >> 2);
            int cb = kq*1024 + e0 + wn*64 + ((lane & 3) << 1);
            #pragma unroll
            for (int ntt = 0; ntt < 8; ntt++){
                float2 v01 = make_float2(acc2[mt][ntt][0], acc2[mt][ntt][1]);
                float2 v23 = make_float2(acc2[mt][ntt][2], acc2[mt][ntt][3]);
                *(float2*)(out + (size_t)rr*DOUT + cb + ntt*8)       = v01;
                *(float2*)(out + (size_t)(rr + 8)*DOUT + cb + ntt*8) = v23;
            }
        }
    }
}

// ------------------------- launch ------------------------------------------
extern "C" void kernel_launch(void* const* d_in, const int* in_sizes, int n_in,
                              void* d_out, int out_size){
    const float* x = (const float*)d_in[0];
    const float* W = (const float*)d_in[1];
    const float* A = (const float*)d_in[2];
    const float* B = (const float*)d_in[3];
    for (int i = 0; i < n_in; i++){
        switch (in_sizes[i]){
            case 16777216: x = (const float*)d_in[i]; break;   // [2,8192,1024]
            case 1769472:  W = (const float*)d_in[i]; break;   // [2304,768]
            case 196608:   A = (const float*)d_in[i]; break;   // [3,1024,64]
            case 147456:   B = (const float*)d_in[i]; break;   // [3,64,768]
            default: break;
        }
    }
    float* out = (float*)d_out;

    cudaFuncSetAttribute(qkv_main, cudaFuncAttributeMaxDynamicSharedMemorySize, SMEM_BYTES);
    qkv_main<<<NCTA, NTHR, SMEM_BYTES>>>(x, W, A, B, out);
}